// round 11
// baseline (speedup 1.0000x reference)
#include <cuda_runtime.h>
#include <cuda_bf16.h>
#include <cfloat>
#include <math.h>

// Problem dims (fixed by the dataset)
#define BN   2048   // batch B
#define DN   128    // feature dim D (also #decoders and output dim)
#define HN   512    // hidden H
#define KP1  513    // HN + 1 prefix rows

// ---------------------------------------------------------------------------
// Scratch (device globals; no allocation allowed)
// ---------------------------------------------------------------------------
__device__ float  g_ench[BN * HN];               // leaky(x@We1^T+be1)
__device__ float  g_enc [BN * DN];               // encoded (B,D)
__device__ float  g_ts  [DN * HN];               // sorted breakpoint keys
__device__ int    g_pos [DN * HN];               // pos[h] = sorted rank of h
__device__ float4 g_arr4[DN * HN];               // sorted (sg, sgt', w1, b1)
__device__ float  g_tab [(size_t)DN * KP1 * 2 * DN]; // interleaved (slope,offs) 67 MB
__device__ int    g_rank[DN * BN];               // [j][b]
__device__ float  g_zt  [DN * BN];               // z[j][b]
__device__ float  g_acc [BN * DN];               // cumsum carry between eval halves

__device__ __forceinline__ float tanh_fast(float x) {
    float y;
    asm("tanh.approx.f32 %0, %1;" : "=f"(y) : "f"(x));
    return y;
}

// ---------------------------------------------------------------------------
// Kernel 1/2: encoder GEMMs   C[m,n] = act(bias[n] + sum_k A[m,k]*B[n,k])
// ACT: 0 = leaky(0.2), 1 = tanh (accurate — error would propagate)
// ---------------------------------------------------------------------------
template<int ACT>
__global__ void gemm_bias_act(const float* __restrict__ A,
                              const float* __restrict__ Bm,
                              const float* __restrict__ bias,
                              float* __restrict__ C,
                              int M, int N, int K)
{
    __shared__ float As[64][33];
    __shared__ float Bs[64][33];

    const int tid = threadIdx.x;
    const int tx = tid & 15;          // n direction
    const int ty = tid >> 4;          // m direction
    const int bm = blockIdx.y * 64;
    const int bn = blockIdx.x * 64;

    float acc[4][4];
#pragma unroll
    for (int i = 0; i < 4; i++)
#pragma unroll
        for (int j = 0; j < 4; j++) acc[i][j] = 0.0f;

    for (int kc = 0; kc < K; kc += 32) {
#pragma unroll
        for (int l = 0; l < 8; l++) {
            int idx = tid + 256 * l;
            int r = idx >> 5, c = idx & 31;
            As[r][c] = A[(size_t)(bm + r) * K + kc + c];
            Bs[r][c] = Bm[(size_t)(bn + r) * K + kc + c];
        }
        __syncthreads();
#pragma unroll
        for (int kk = 0; kk < 32; kk++) {
            float a[4], b[4];
#pragma unroll
            for (int i = 0; i < 4; i++) a[i] = As[ty * 4 + i][kk];
#pragma unroll
            for (int j = 0; j < 4; j++) b[j] = Bs[tx * 4 + j][kk];
#pragma unroll
            for (int i = 0; i < 4; i++)
#pragma unroll
                for (int j = 0; j < 4; j++)
                    acc[i][j] = fmaf(a[i], b[j], acc[i][j]);
        }
        __syncthreads();
    }

#pragma unroll
    for (int i = 0; i < 4; i++) {
        int m = bm + ty * 4 + i;
#pragma unroll
        for (int j = 0; j < 4; j++) {
            int n = bn + tx * 4 + j;
            float v = acc[i][j] + bias[n];
            if (ACT == 0) v = (v >= 0.0f) ? v : 0.2f * v;
            else          v = tanhf(v);
            C[(size_t)m * N + n] = v;
        }
    }
}

// ---------------------------------------------------------------------------
// Kernel 3: per-j bitonic sort of 512 breakpoints.
// Emits g_ts (sorted keys), g_pos (h -> sorted rank), and the packed sorted
// scalar array g_arr4[k] = (sg, sgt', w1, b1); degenerate X term folded into
// sgt' (degenerate rows sort to the tail -> never ranked-into).
// ---------------------------------------------------------------------------
__global__ void sort_breakpoints(const float* __restrict__ W1s,
                                 const float* __restrict__ b1s)
{
    __shared__ float key[HN];
    __shared__ int   idx[HN];
    const int j = blockIdx.x;
    const int h = threadIdx.x;

    float w1 = W1s[j * HN + h];
    float b1 = b1s[j * HN + h];
    float t  = -b1 / w1;
    bool fin = (w1 != 0.0f) && isfinite(t);
    key[h] = fin ? t : FLT_MAX;
    idx[h] = h;
    __syncthreads();

    for (int size = 2; size <= HN; size <<= 1) {
        for (int stride = size >> 1; stride > 0; stride >>= 1) {
            int p = h ^ stride;
            if (p > h) {
                bool asc = ((h & size) == 0);
                float kh = key[h], kp = key[p];
                if ((kh > kp) == asc) {
                    key[h] = kp; key[p] = kh;
                    int th = idx[h]; idx[h] = idx[p]; idx[p] = th;
                }
            }
            __syncthreads();
        }
    }
    float tk  = key[h];
    int   ho  = idx[h];
    float w1o = W1s[j * HN + ho];
    float b1o = b1s[j * HN + ho];
    bool  fo  = (tk != FLT_MAX);

    g_ts [j * HN + h]  = tk;
    g_pos[j * HN + ho] = h;
    float sg  = fo ? 0.4f * fabsf(w1o) : 0.0f;
    float sgt = fo ? sg * tk           : 0.4f * fabsf(b1o);
    g_arr4[j * HN + h] = make_float4(sg, sgt, w1o, b1o);
}

// ---------------------------------------------------------------------------
// Kernel 4 (fused): stage W2 tile PRE-PERMUTED into sorted-k order in smem,
// then chunked prefix scan + direct table write.  j = blockIdx.y + j_base.
// ---------------------------------------------------------------------------
#define W2PITCH 513
__global__ __launch_bounds__(512) void build_tables_fused(
    const float* __restrict__ W2s, const float* __restrict__ b2s, int j_base)
{
    extern __shared__ float sm[];
    float4* arr4_s = (float4*)sm;                    // [512]
    float*  w2_s   = sm + 4 * HN;                    // [32][W2PITCH]
    int*    pos_s  = (int*)(w2_s + 32 * W2PITCH);    // [512]
    float*  pg     = (float*)(pos_s + HN);           // [16][32] each
    float*  pq     = pg + 512;
    float*  pa     = pq + 512;
    float*  pc     = pa + 512;

    const int j   = blockIdx.y + j_base;
    const int d0  = blockIdx.x * 32;
    const int tid = threadIdx.x;

    {
        int i = tid;
        pos_s [i] = g_pos [j * HN + i];
        arr4_s[i] = g_arr4[j * HN + i];
    }
    __syncthreads();

    const float4* src = reinterpret_cast<const float4*>(
        W2s + ((size_t)j * DN + d0) * HN);
#pragma unroll
    for (int l = 0; l < 8; l++) {
        int idx = l * 512 + tid;
        int d = idx >> 7, hq = idx & 127;
        float4 v = src[d * (HN / 4) + hq];
        float* row = w2_s + d * W2PITCH;
        int hb = hq * 4;
        row[pos_s[hb + 0]] = v.x;
        row[pos_s[hb + 1]] = v.y;
        row[pos_s[hb + 2]] = v.z;
        row[pos_s[hb + 3]] = v.w;
    }
    __syncthreads();

    const int dl = tid & 31;
    const int c  = tid >> 5;
    const int k0 = c * 32;
    const float* wme = w2_s + dl * W2PITCH;

    float ga = 0.f, qa = 0.f, aa = 0.f, ca = 0.f;
#pragma unroll
    for (int i = 0; i < 32; i++) {
        int kk = k0 + i;
        float  w2 = wme[kk];
        float4 s  = arr4_s[kk];
        ga = fmaf(s.x, w2, ga);
        qa = fmaf(s.y, w2, qa);
        aa = fmaf(s.z, w2, aa);
        ca = fmaf(s.w, w2, ca);
    }
    pg[c * 32 + dl] = ga; pq[c * 32 + dl] = qa;
    pa[c * 32 + dl] = aa; pc[c * 32 + dl] = ca;
    __syncthreads();

    float A = 0.f, C = 0.f, G = 0.f, Qt = 0.f, Pcar = 0.f, Qcar = 0.f;
#pragma unroll
    for (int cc = 0; cc < 16; cc++) {
        float g = pg[cc * 32 + dl], q = pq[cc * 32 + dl];
        A += pa[cc * 32 + dl]; C += pc[cc * 32 + dl];
        G += g; Qt += q;
        if (cc < c) { Pcar += g; Qcar += q; }
    }

    const float base_s = 0.6f * A - G;
    const float base_o = 0.6f * C + Qt + b2s[j * DN + d0 + dl];
    float* __restrict__ tj = g_tab + (size_t)j * KP1 * (2 * DN);
    if (c == 0) {
        *reinterpret_cast<float2*>(tj + 2 * (d0 + dl)) = make_float2(base_s, base_o);
    }

    float P = Pcar, Q = Qcar;
#pragma unroll
    for (int i = 0; i < 32; i++) {
        int kk = k0 + i;
        float  w2 = wme[kk];
        float4 s  = arr4_s[kk];
        P = fmaf(s.x, w2, P);
        Q = fmaf(s.y, w2, Q);
        float2 v = make_float2(fmaf(2.0f, P, base_s), fmaf(-2.0f, Q, base_o));
        *reinterpret_cast<float2*>(
            tj + (size_t)(kk + 1) * (2 * DN) + 2 * (d0 + dl)) = v;
    }
}

// ---------------------------------------------------------------------------
// Kernel 5: rank(z) per (j,b), breakpoints staged in smem
// ---------------------------------------------------------------------------
__global__ __launch_bounds__(512) void rank_kernel()
{
    __shared__ float ts_s[HN];
    const int j = blockIdx.x;
    const int b = blockIdx.y * 512 + threadIdx.x;
    for (int i = threadIdx.x; i < HN; i += 512) ts_s[i] = g_ts[j * HN + i];
    __syncthreads();

    float z = g_enc[b * DN + j];
    int lo = 0, hi = HN;
    while (lo < hi) {
        int mid = (lo + hi) >> 1;
        if (ts_s[mid] <= z) lo = mid + 1; else hi = mid;
    }
    g_rank[j * BN + b] = lo;
    g_zt  [j * BN + b] = z;
}

// ---------------------------------------------------------------------------
// Kernel 6: evaluate + cumsum + tanh over a j-half [J0, J0+64).
// block = 2 b's, 8 warps: warp = (b_local, d-quarter); lane owns ONE d via
// float2 table loads.  grid = 1024 blocks -> 8192 warps (~55/SM) for latency
// hiding.  __ldg table reads, __stcs streaming stores, exact fp32 carry.
// ---------------------------------------------------------------------------
template<int J0, bool LOAD_CARRY, bool SAVE_CARRY>
__global__ __launch_bounds__(256) void eval_kernel(float* __restrict__ out)
{
    __shared__ float z_s[64][2];
    __shared__ int   k_s[64][2];

    const int b0   = blockIdx.x * 2;
    const int w    = threadIdx.x >> 5;
    const int bl   = w >> 2;               // b_local 0..1
    const int quar = w & 3;                // d-quarter 0..3
    const int lane = threadIdx.x & 31;

    if (threadIdx.x < 128) {
        int jj = threadIdx.x >> 1, b2 = threadIdx.x & 1;
        z_s[jj][b2] = g_zt  [(J0 + jj) * BN + b0 + b2];
        k_s[jj][b2] = g_rank[(J0 + jj) * BN + b0 + b2];
    }
    __syncthreads();

    const int b = b0 + bl;
    const int d = quar * 32 + lane;
    const int toff = 2 * d;                    // offset into 256-float row
    const size_t cidx = (size_t)b * DN + d;

    float a0 = 0.f;
    if (LOAD_CARRY) a0 = g_acc[cidx];

#pragma unroll 8
    for (int jj = 0; jj < 64; jj++) {
        float z = z_s[jj][bl];
        int   k = k_s[jj][bl];
        const float2 u = __ldg(reinterpret_cast<const float2*>(
            g_tab + (size_t)((J0 + jj) * KP1 + k) * (2 * DN) + toff));

        a0 += fmaf(u.x, z, u.y);

        __stcs(out + ((size_t)(J0 + jj) * BN + b) * DN + d, tanh_fast(a0));
    }

    if (SAVE_CARRY) __stcs(g_acc + cidx, a0);
}

// ---------------------------------------------------------------------------
// Launch — pipeline (R9 structure):
//   sB  : enc1 -> enc2 -> rank (after sort) -> eval(j<64) (after buildA)
//   main: sort -> buildA (j<64) -> buildB (j>=64) -> eval(j>=64) (after eval1)
// ---------------------------------------------------------------------------
extern "C" void kernel_launch(void* const* d_in, const int* in_sizes, int n_in,
                              void* d_out, int out_size)
{
    const float* x   = (const float*)d_in[0];   // (2048,128)
    const float* We1 = (const float*)d_in[1];   // (512,128)
    const float* be1 = (const float*)d_in[2];   // (512,)
    const float* We2 = (const float*)d_in[3];   // (128,512)
    const float* be2 = (const float*)d_in[4];   // (128,)
    const float* W1s = (const float*)d_in[5];   // (128,512)
    const float* b1s = (const float*)d_in[6];   // (128,512)
    const float* W2s = (const float*)d_in[7];   // (128,128,512)
    const float* b2s = (const float*)d_in[8];   // (128,128)
    float* out = (float*)d_out;                 // (128,2048,128)

    float* ench; cudaGetSymbolAddress((void**)&ench, g_ench);
    float* enc;  cudaGetSymbolAddress((void**)&enc,  g_enc);

    static cudaStream_t sB = nullptr;
    static cudaEvent_t evFork = nullptr, evSort = nullptr,
                       evBuildA = nullptr, evEval1 = nullptr;
    static int build_smem = 0;
    if (sB == nullptr) {
        cudaStreamCreateWithFlags(&sB, cudaStreamNonBlocking);
        cudaEventCreateWithFlags(&evFork,   cudaEventDisableTiming);
        cudaEventCreateWithFlags(&evSort,   cudaEventDisableTiming);
        cudaEventCreateWithFlags(&evBuildA, cudaEventDisableTiming);
        cudaEventCreateWithFlags(&evEval1,  cudaEventDisableTiming);
        build_smem = (4 * HN + 32 * W2PITCH + HN /*pos*/ + 4 * 512) * (int)sizeof(float);
        cudaFuncSetAttribute(build_tables_fused,
                             cudaFuncAttributeMaxDynamicSharedMemorySize, build_smem);
    }

    // Fork: encoder on side stream
    cudaEventRecord(evFork, 0);
    cudaStreamWaitEvent(sB, evFork, 0);
    gemm_bias_act<0><<<dim3(HN / 64, BN / 64), 256, 0, sB>>>(x,    We1, be1, ench, BN, HN, DN);
    gemm_bias_act<1><<<dim3(DN / 64, BN / 64), 256, 0, sB>>>(ench, We2, be2, enc,  BN, DN, HN);

    // Main stream: sort, then first-half table build
    sort_breakpoints<<<DN, HN>>>(W1s, b1s);
    cudaEventRecord(evSort, 0);
    build_tables_fused<<<dim3(DN / 32, 64), 512, build_smem>>>(W2s, b2s, 0);
    cudaEventRecord(evBuildA, 0);
    // Second-half build overlaps eval1 (different streams, different j rows)
    build_tables_fused<<<dim3(DN / 32, 64), 512, build_smem>>>(W2s, b2s, 64);

    // Side stream: rank (needs sort + encoder), then eval of first j-half
    cudaStreamWaitEvent(sB, evSort, 0);
    rank_kernel<<<dim3(DN, BN / 512), 512, 0, sB>>>();
    cudaStreamWaitEvent(sB, evBuildA, 0);
    eval_kernel<0, false, true><<<BN / 2, 256, 0, sB>>>(out);
    cudaEventRecord(evEval1, sB);

    // Main: second j-half eval after buildB (in-order) + eval1 carry
    cudaStreamWaitEvent(0, evEval1, 0);
    eval_kernel<64, true, false><<<BN / 2, 256>>>(out);
}

// round 13
// speedup vs baseline: 1.4568x; 1.4568x over previous
#include <cuda_runtime.h>
#include <cuda_bf16.h>
#include <cfloat>
#include <math.h>

// Problem dims (fixed by the dataset)
#define BN   2048   // batch B
#define DN   128    // feature dim D (also #decoders and output dim)
#define HN   512    // hidden H
#define KP1  513    // HN + 1 prefix rows

// ---------------------------------------------------------------------------
// Scratch (device globals; no allocation allowed)
// ---------------------------------------------------------------------------
__device__ float  g_ench[BN * HN];               // leaky(x@We1^T+be1)
__device__ float  g_enc [BN * DN];               // encoded (B,D)
__device__ float  g_ts  [DN * HN];               // sorted breakpoint keys
__device__ int    g_pos [DN * HN];               // pos[h] = sorted rank of h
__device__ float4 g_arr4[DN * HN];               // sorted (sg, sgt', w1, b1)
__device__ float  g_tab [(size_t)DN * KP1 * 2 * DN]; // interleaved (slope,offs) 67 MB
__device__ int    g_rank[DN * BN];               // [j][b]
__device__ float  g_zt  [DN * BN];               // z[j][b]
__device__ float  g_acc [BN * DN];               // cumsum carry between eval j-halves

__device__ __forceinline__ float tanh_fast(float x) {
    float y;
    asm("tanh.approx.f32 %0, %1;" : "=f"(y) : "f"(x));
    return y;
}

// ---------------------------------------------------------------------------
// Kernel 1/2: encoder GEMMs   C[m,n] = act(bias[n] + sum_k A[m,k]*B[n,k])
// ACT: 0 = leaky(0.2), 1 = tanh (accurate — error would propagate)
// ---------------------------------------------------------------------------
template<int ACT>
__global__ void gemm_bias_act(const float* __restrict__ A,
                              const float* __restrict__ Bm,
                              const float* __restrict__ bias,
                              float* __restrict__ C,
                              int M, int N, int K)
{
    __shared__ float As[64][33];
    __shared__ float Bs[64][33];

    const int tid = threadIdx.x;
    const int tx = tid & 15;          // n direction
    const int ty = tid >> 4;          // m direction
    const int bm = blockIdx.y * 64;
    const int bn = blockIdx.x * 64;

    float acc[4][4];
#pragma unroll
    for (int i = 0; i < 4; i++)
#pragma unroll
        for (int j = 0; j < 4; j++) acc[i][j] = 0.0f;

    for (int kc = 0; kc < K; kc += 32) {
#pragma unroll
        for (int l = 0; l < 8; l++) {
            int idx = tid + 256 * l;
            int r = idx >> 5, c = idx & 31;
            As[r][c] = A[(size_t)(bm + r) * K + kc + c];
            Bs[r][c] = Bm[(size_t)(bn + r) * K + kc + c];
        }
        __syncthreads();
#pragma unroll
        for (int kk = 0; kk < 32; kk++) {
            float a[4], b[4];
#pragma unroll
            for (int i = 0; i < 4; i++) a[i] = As[ty * 4 + i][kk];
#pragma unroll
            for (int j = 0; j < 4; j++) b[j] = Bs[tx * 4 + j][kk];
#pragma unroll
            for (int i = 0; i < 4; i++)
#pragma unroll
                for (int j = 0; j < 4; j++)
                    acc[i][j] = fmaf(a[i], b[j], acc[i][j]);
        }
        __syncthreads();
    }

#pragma unroll
    for (int i = 0; i < 4; i++) {
        int m = bm + ty * 4 + i;
#pragma unroll
        for (int j = 0; j < 4; j++) {
            int n = bn + tx * 4 + j;
            float v = acc[i][j] + bias[n];
            if (ACT == 0) v = (v >= 0.0f) ? v : 0.2f * v;
            else          v = tanhf(v);
            C[(size_t)m * N + n] = v;
        }
    }
}

// ---------------------------------------------------------------------------
// Kernel 3: per-j bitonic sort of 512 breakpoints (j = blockIdx.x + j_base).
// Emits g_ts, g_pos, and packed sorted scalars g_arr4[k] = (sg, sgt', w1, b1);
// degenerate X term folded into sgt' (degenerate rows sort to the tail ->
// never ranked-into).
// ---------------------------------------------------------------------------
__global__ void sort_breakpoints(const float* __restrict__ W1s,
                                 const float* __restrict__ b1s, int j_base)
{
    __shared__ float key[HN];
    __shared__ int   idx[HN];
    const int j = blockIdx.x + j_base;
    const int h = threadIdx.x;

    float w1 = W1s[j * HN + h];
    float b1 = b1s[j * HN + h];
    float t  = -b1 / w1;
    bool fin = (w1 != 0.0f) && isfinite(t);
    key[h] = fin ? t : FLT_MAX;
    idx[h] = h;
    __syncthreads();

    for (int size = 2; size <= HN; size <<= 1) {
        for (int stride = size >> 1; stride > 0; stride >>= 1) {
            int p = h ^ stride;
            if (p > h) {
                bool asc = ((h & size) == 0);
                float kh = key[h], kp = key[p];
                if ((kh > kp) == asc) {
                    key[h] = kp; key[p] = kh;
                    int th = idx[h]; idx[h] = idx[p]; idx[p] = th;
                }
            }
            __syncthreads();
        }
    }
    float tk  = key[h];
    int   ho  = idx[h];
    float w1o = W1s[j * HN + ho];
    float b1o = b1s[j * HN + ho];
    bool  fo  = (tk != FLT_MAX);

    g_ts [j * HN + h]  = tk;
    g_pos[j * HN + ho] = h;
    float sg  = fo ? 0.4f * fabsf(w1o) : 0.0f;
    float sgt = fo ? sg * tk           : 0.4f * fabsf(b1o);
    g_arr4[j * HN + h] = make_float4(sg, sgt, w1o, b1o);
}

// ---------------------------------------------------------------------------
// Kernel 4 (fused): stage W2 tile PRE-PERMUTED into sorted-k order in smem,
// then chunked prefix scan + direct table write.  j = blockIdx.y + j_base.
// ---------------------------------------------------------------------------
#define W2PITCH 513
__global__ __launch_bounds__(512) void build_tables_fused(
    const float* __restrict__ W2s, const float* __restrict__ b2s, int j_base)
{
    extern __shared__ float sm[];
    float4* arr4_s = (float4*)sm;                    // [512]
    float*  w2_s   = sm + 4 * HN;                    // [32][W2PITCH]
    int*    pos_s  = (int*)(w2_s + 32 * W2PITCH);    // [512]
    float*  pg     = (float*)(pos_s + HN);           // [16][32] each
    float*  pq     = pg + 512;
    float*  pa     = pq + 512;
    float*  pc     = pa + 512;

    const int j   = blockIdx.y + j_base;
    const int d0  = blockIdx.x * 32;
    const int tid = threadIdx.x;

    {
        int i = tid;
        pos_s [i] = g_pos [j * HN + i];
        arr4_s[i] = g_arr4[j * HN + i];
    }
    __syncthreads();

    const float4* src = reinterpret_cast<const float4*>(
        W2s + ((size_t)j * DN + d0) * HN);
#pragma unroll
    for (int l = 0; l < 8; l++) {
        int idx = l * 512 + tid;
        int d = idx >> 7, hq = idx & 127;
        float4 v = src[d * (HN / 4) + hq];
        float* row = w2_s + d * W2PITCH;
        int hb = hq * 4;
        row[pos_s[hb + 0]] = v.x;
        row[pos_s[hb + 1]] = v.y;
        row[pos_s[hb + 2]] = v.z;
        row[pos_s[hb + 3]] = v.w;
    }
    __syncthreads();

    const int dl = tid & 31;
    const int c  = tid >> 5;
    const int k0 = c * 32;
    const float* wme = w2_s + dl * W2PITCH;

    float ga = 0.f, qa = 0.f, aa = 0.f, ca = 0.f;
#pragma unroll
    for (int i = 0; i < 32; i++) {
        int kk = k0 + i;
        float  w2 = wme[kk];
        float4 s  = arr4_s[kk];
        ga = fmaf(s.x, w2, ga);
        qa = fmaf(s.y, w2, qa);
        aa = fmaf(s.z, w2, aa);
        ca = fmaf(s.w, w2, ca);
    }
    pg[c * 32 + dl] = ga; pq[c * 32 + dl] = qa;
    pa[c * 32 + dl] = aa; pc[c * 32 + dl] = ca;
    __syncthreads();

    float A = 0.f, C = 0.f, G = 0.f, Qt = 0.f, Pcar = 0.f, Qcar = 0.f;
#pragma unroll
    for (int cc = 0; cc < 16; cc++) {
        float g = pg[cc * 32 + dl], q = pq[cc * 32 + dl];
        A += pa[cc * 32 + dl]; C += pc[cc * 32 + dl];
        G += g; Qt += q;
        if (cc < c) { Pcar += g; Qcar += q; }
    }

    const float base_s = 0.6f * A - G;
    const float base_o = 0.6f * C + Qt + b2s[j * DN + d0 + dl];
    float* __restrict__ tj = g_tab + (size_t)j * KP1 * (2 * DN);
    if (c == 0) {
        *reinterpret_cast<float2*>(tj + 2 * (d0 + dl)) = make_float2(base_s, base_o);
    }

    float P = Pcar, Q = Qcar;
#pragma unroll
    for (int i = 0; i < 32; i++) {
        int kk = k0 + i;
        float  w2 = wme[kk];
        float4 s  = arr4_s[kk];
        P = fmaf(s.x, w2, P);
        Q = fmaf(s.y, w2, Q);
        float2 v = make_float2(fmaf(2.0f, P, base_s), fmaf(-2.0f, Q, base_o));
        *reinterpret_cast<float2*>(
            tj + (size_t)(kk + 1) * (2 * DN) + 2 * (d0 + dl)) = v;
    }
}

// ---------------------------------------------------------------------------
// Kernel 5: rank(z) per (j,b), breakpoints staged in smem
// ---------------------------------------------------------------------------
__global__ __launch_bounds__(512) void rank_kernel()
{
    __shared__ float ts_s[HN];
    const int j = blockIdx.x;
    const int b = blockIdx.y * 512 + threadIdx.x;
    for (int i = threadIdx.x; i < HN; i += 512) ts_s[i] = g_ts[j * HN + i];
    __syncthreads();

    float z = g_enc[b * DN + j];
    int lo = 0, hi = HN;
    while (lo < hi) {
        int mid = (lo + hi) >> 1;
        if (ts_s[mid] <= z) lo = mid + 1; else hi = mid;
    }
    g_rank[j * BN + b] = lo;
    g_zt  [j * BN + b] = z;
}

// ---------------------------------------------------------------------------
// Kernel 6: evaluate + cumsum + tanh over a j-half [J0, J0+64) and b range
// [b_base, b_base+1024).  R9-proven shape: block = 4 b's, 8 warps =
// (b_local, d-half), 64 d per warp via one float4/lane/j.
// __ldg table reads, __stcs streaming stores, exact fp32 carry via g_acc.
// ---------------------------------------------------------------------------
template<int J0, bool LOAD_CARRY, bool SAVE_CARRY>
__global__ __launch_bounds__(256) void eval_kernel(float* __restrict__ out,
                                                   int b_base)
{
    __shared__ float z_s[64][4];
    __shared__ int   k_s[64][4];

    const int b0   = b_base + blockIdx.x * 4;
    const int w    = threadIdx.x >> 5;
    const int bl   = w >> 1;               // b_local 0..3
    const int half = w & 1;                // d-half 0/1
    const int lane = threadIdx.x & 31;

    for (int i = threadIdx.x; i < 64 * 4; i += 256) {
        int jj = i >> 2, b2 = i & 3;
        z_s[jj][b2] = g_zt  [(J0 + jj) * BN + b0 + b2];
        k_s[jj][b2] = g_rank[(J0 + jj) * BN + b0 + b2];
    }
    __syncthreads();

    const int b = b0 + bl;
    const int toff = half * DN + lane * 4;     // offset into 256-float row
    const size_t cidx = (size_t)b * DN + half * 64 + 2 * lane;

    float a0 = 0.f, a1 = 0.f;
    if (LOAD_CARRY) {
        float2 cv = *reinterpret_cast<const float2*>(g_acc + cidx);
        a0 = cv.x; a1 = cv.y;
    }

#pragma unroll 8
    for (int jj = 0; jj < 64; jj++) {
        float z = z_s[jj][bl];
        int   k = k_s[jj][bl];
        const float4 u = __ldg(reinterpret_cast<const float4*>(
            g_tab + (size_t)((J0 + jj) * KP1 + k) * (2 * DN) + toff));

        a0 += fmaf(u.x, z, u.y);
        a1 += fmaf(u.z, z, u.w);

        float* op = out + ((size_t)(J0 + jj) * BN + b) * DN + half * 64 + 2 * lane;
        __stcs(reinterpret_cast<float2*>(op),
               make_float2(tanh_fast(a0), tanh_fast(a1)));
    }

    if (SAVE_CARRY) {
        __stcs(reinterpret_cast<float2*>(g_acc + cidx), make_float2(a0, a1));
    }
}

// ---------------------------------------------------------------------------
// Launch — b-split dual eval pipelines (cumsum chains are per-b independent):
//   main: sortA -> sortB -> buildA -> buildB -> evalB1(b>=1024,j<64) -> evalB2
//   sB  : enc1 -> enc2 -> rank -> evalA1(b<1024,j<64) -> evalA2
// Final join: main waits on sB's last event (graph capture requires all
// side-stream work to rejoin the origin stream).
// ---------------------------------------------------------------------------
extern "C" void kernel_launch(void* const* d_in, const int* in_sizes, int n_in,
                              void* d_out, int out_size)
{
    const float* x   = (const float*)d_in[0];   // (2048,128)
    const float* We1 = (const float*)d_in[1];   // (512,128)
    const float* be1 = (const float*)d_in[2];   // (512,)
    const float* We2 = (const float*)d_in[3];   // (128,512)
    const float* be2 = (const float*)d_in[4];   // (128,)
    const float* W1s = (const float*)d_in[5];   // (128,512)
    const float* b1s = (const float*)d_in[6];   // (128,512)
    const float* W2s = (const float*)d_in[7];   // (128,128,512)
    const float* b2s = (const float*)d_in[8];   // (128,128)
    float* out = (float*)d_out;                 // (128,2048,128)

    float* ench; cudaGetSymbolAddress((void**)&ench, g_ench);
    float* enc;  cudaGetSymbolAddress((void**)&enc,  g_enc);

    static cudaStream_t sB = nullptr;
    static cudaEvent_t evFork = nullptr, evSort = nullptr, evBuildA = nullptr,
                       evBuildB = nullptr, evRank = nullptr, evDone = nullptr;
    static int build_smem = 0;
    if (sB == nullptr) {
        cudaStreamCreateWithFlags(&sB, cudaStreamNonBlocking);
        cudaEventCreateWithFlags(&evFork,   cudaEventDisableTiming);
        cudaEventCreateWithFlags(&evSort,   cudaEventDisableTiming);
        cudaEventCreateWithFlags(&evBuildA, cudaEventDisableTiming);
        cudaEventCreateWithFlags(&evBuildB, cudaEventDisableTiming);
        cudaEventCreateWithFlags(&evRank,   cudaEventDisableTiming);
        cudaEventCreateWithFlags(&evDone,   cudaEventDisableTiming);
        build_smem = (4 * HN + 32 * W2PITCH + HN /*pos*/ + 4 * 512) * (int)sizeof(float);
        cudaFuncSetAttribute(build_tables_fused,
                             cudaFuncAttributeMaxDynamicSharedMemorySize, build_smem);
    }

    // Fork: encoder on side stream
    cudaEventRecord(evFork, 0);
    cudaStreamWaitEvent(sB, evFork, 0);
    gemm_bias_act<0><<<dim3(HN / 64, BN / 64), 256, 0, sB>>>(x,    We1, be1, ench, BN, HN, DN);
    gemm_bias_act<1><<<dim3(DN / 64, BN / 64), 256, 0, sB>>>(ench, We2, be2, enc,  BN, DN, HN);

    // Main stream: sort halves, then build halves
    sort_breakpoints<<<64, HN>>>(W1s, b1s, 0);
    sort_breakpoints<<<64, HN>>>(W1s, b1s, 64);
    cudaEventRecord(evSort, 0);
    build_tables_fused<<<dim3(DN / 32, 64), 512, build_smem>>>(W2s, b2s, 0);
    cudaEventRecord(evBuildA, 0);
    build_tables_fused<<<dim3(DN / 32, 64), 512, build_smem>>>(W2s, b2s, 64);
    cudaEventRecord(evBuildB, 0);

    // Side stream: rank (needs encoder + full sort)
    cudaStreamWaitEvent(sB, evSort, 0);
    rank_kernel<<<dim3(DN, BN / 512), 512, 0, sB>>>();
    cudaEventRecord(evRank, sB);

    // Side stream eval pipeline: b < 1024
    cudaStreamWaitEvent(sB, evBuildA, 0);
    eval_kernel<0,  false, true ><<<256, 256, 0, sB>>>(out, 0);
    cudaStreamWaitEvent(sB, evBuildB, 0);
    eval_kernel<64, true,  false><<<256, 256, 0, sB>>>(out, 0);
    cudaEventRecord(evDone, sB);

    // Main stream eval pipeline: b >= 1024 (builds already in-stream)
    cudaStreamWaitEvent(0, evRank, 0);
    eval_kernel<0,  false, true ><<<256, 256>>>(out, 1024);
    eval_kernel<64, true,  false><<<256, 256>>>(out, 1024);

    // Join side stream back into the capture origin
    cudaStreamWaitEvent(0, evDone, 0);
}